// round 6
// baseline (speedup 1.0000x reference)
#include <cuda_runtime.h>
#include <cuda_bf16.h>

// Multilevel DB4 DWT (11 levels), register cascade, fully coalesced I/O.
// 1024 threads/CTA, thread t owns x[4t..4t+4) via ONE LDG.128 (16B lane
// stride -> perfectly coalesced). Levels 0-1 in registers with a 2-float
// neighbor exchange per level; every d-store to global is perfectly
// coalesced. Levels 2-3 via smem halving stages; levels 4-10 by warp 0.
//
// Boundary (matches reference W[:L,:L] slicing):
//   level 0 : periodic wrap; level >=1: taps beyond L are zero.

#define DWT_N 4096
#define NTH   1024

__device__ __forceinline__ void dwt_pair(float x0, float x1, float x2, float x3,
                                         float& a, float& d)
{
    const float c0 =  0.4829629131445341f;
    const float c1 =  0.8365163037378079f;
    const float c2 =  0.2241438680420134f;
    const float c3 = -0.1294095225512604f;
    a = c0 * x0 + c1 * x1 + c2 * x2 + c3 * x3;
    d = c3 * x0 - c2 * x1 + c1 * x2 - c0 * x3;
}

__global__ __launch_bounds__(NTH)
void dwt_db4_reg1024_kernel(const float* __restrict__ in,
                            float* __restrict__ out)
{
    __shared__ float exA[2 * NTH];   // exchange ping (8KB)
    __shared__ float exB[2 * NTH];   // exchange pong (8KB)
    __shared__ float sm2[1024];      // level-2 input (4KB)
    __shared__ float sm3[512];       // level-3 input (2KB)
    __shared__ float sm4[256];       // levels 4-10 signal (1KB)

    const int t = threadIdx.x;
    const float* src = in  + (size_t)blockIdx.x * DWT_N;
    float*       dst = out + (size_t)blockIdx.x * DWT_N;

    // ---- load chunk x[4t .. 4t+4) : 1x LDG.128, perfectly coalesced ----
    float v[4];
    {
        float4 f = reinterpret_cast<const float4*>(src)[t];
        v[0] = f.x; v[1] = f.y; v[2] = f.z; v[3] = f.w;
    }

    // ================= level 0 (L=4096): periodic wrap =================
    *reinterpret_cast<float2*>(&exA[2 * t]) = make_float2(v[0], v[1]);
    __syncthreads();
    float2 nb = *reinterpret_cast<const float2*>(&exA[2 * ((t + 1) & (NTH - 1))]);

    float a0[2], d0[2];
    dwt_pair(v[0], v[1], v[2], v[3], a0[0], d0[0]);
    dwt_pair(v[2], v[3], nb.x, nb.y, a0[1], d0[1]);
    // d0 -> out[2048 + 2t), float2, 8B lane stride: perfectly coalesced
    *reinterpret_cast<float2*>(dst + 2048 + 2 * t) = make_float2(d0[0], d0[1]);

    // ================= level 1 (L=2048): truncated =================
    *reinterpret_cast<float2*>(&exB[2 * t]) = make_float2(a0[0], a0[1]);
    __syncthreads();
    nb = (t == NTH - 1) ? make_float2(0.f, 0.f)
                        : *reinterpret_cast<const float2*>(&exB[2 * (t + 1)]);

    float a1, d1;
    dwt_pair(a0[0], a0[1], nb.x, nb.y, a1, d1);
    dst[1024 + t] = d1;                     // perfectly coalesced

    // ---- a1 (1024 values) -> smem for level 2 ----
    sm2[t] = a1;
    __syncthreads();

    // ================= level 2 (L=1024): truncated, 512 threads =========
    if (t < 512) {
        float2 xa = *reinterpret_cast<const float2*>(&sm2[2 * t]);
        float2 xb = (2 * t + 2 < 1024)
                  ? *reinterpret_cast<const float2*>(&sm2[2 * t + 2])
                  : make_float2(0.f, 0.f);
        float a2, d2;
        dwt_pair(xa.x, xa.y, xb.x, xb.y, a2, d2);
        dst[512 + t] = d2;
        sm3[t] = a2;
    }
    __syncthreads();

    // ================= level 3 (L=512): truncated, 256 threads ==========
    if (t < 256) {
        float2 xa = *reinterpret_cast<const float2*>(&sm3[2 * t]);
        float2 xb = (2 * t + 2 < 512)
                  ? *reinterpret_cast<const float2*>(&sm3[2 * t + 2])
                  : make_float2(0.f, 0.f);
        float a3, d3;
        dwt_pair(xa.x, xa.y, xb.x, xb.y, a3, d3);
        dst[256 + t] = d3;
        sm4[t] = a3;
    }
    __syncthreads();

    // ================= levels 4-10 on sm4[0:256): warp 0 ================
    if (t < 32) {
        #pragma unroll
        for (int l = 0; l < 7; ++l) {
            const int L = 256 >> l;
            const int H = L >> 1;
            float ra[4], rd[4];
            int cnt = 0;
            #pragma unroll
            for (int k = t; k < H; k += 32) {
                float x0 = sm4[2*k],     x1 = sm4[2*k + 1];
                float x2 = (2*k + 2 < L) ? sm4[2*k + 2] : 0.f;
                float x3 = (2*k + 3 < L) ? sm4[2*k + 3] : 0.f;
                dwt_pair(x0, x1, x2, x3, ra[cnt], rd[cnt]);
                ++cnt;
            }
            __syncwarp();
            cnt = 0;
            #pragma unroll
            for (int k = t; k < H; k += 32) {
                sm4[k]     = ra[cnt];
                sm4[H + k] = rd[cnt];
                ++cnt;
            }
            __syncwarp();
        }
        // out[0:256) final
        #pragma unroll
        for (int i = t; i < 64; i += 32)
            reinterpret_cast<float4*>(dst)[i] =
                reinterpret_cast<const float4*>(sm4)[i];
    }
}

extern "C" void kernel_launch(void* const* d_in, const int* in_sizes, int n_in,
                              void* d_out, int out_size)
{
    const float* x = (const float*)d_in[0];   // [B, N] float32
    // d_in[1] = W : structure known analytically; unused.
    float* out = (float*)d_out;

    const int B = in_sizes[0] / DWT_N;        // 4096 rows
    dwt_db4_reg1024_kernel<<<B, NTH>>>(x, out);
}

// round 7
// speedup vs baseline: 1.1912x; 1.1912x over previous
#include <cuda_runtime.h>
#include <cuda_bf16.h>

// Multilevel DB4 DWT (11 levels), register cascade + smem-staged load.
// 256 threads/CTA, thread t owns x[16t..16t+16).
//   - Row loaded gmem->smem fully coalesced (4x LDG.128/thread, 1x wavefronts),
//     then read back as conflict-free LDS.128 via float4-padded layout.
//   - Levels 0-3 in registers (2-float neighbor exchange/level), d-outputs
//     stored straight to global. Levels 4-10 (256 values) by warp 0.
//
// Boundary (matches reference W[:L,:L] slicing):
//   level 0 : periodic wrap; level >=1: taps beyond L are zero.

#define DWT_N 4096
#define NTH   256

__device__ __forceinline__ void dwt_pair(float x0, float x1, float x2, float x3,
                                         float& a, float& d)
{
    const float c0 =  0.4829629131445341f;
    const float c1 =  0.8365163037378079f;
    const float c2 =  0.2241438680420134f;
    const float c3 = -0.1294095225512604f;
    a = c0 * x0 + c1 * x1 + c2 * x2 + c3 * x3;
    d = c3 * x0 - c2 * x1 + c1 * x2 - c0 * x3;
}

__global__ __launch_bounds__(NTH)
void dwt_db4_staged_kernel(const float* __restrict__ in,
                           float* __restrict__ out)
{
    // Staging buffer: 1024 float4 + 1 pad-float4 per 4 -> 1280 float4 (20KB).
    __shared__ float4 st[1280];
    __shared__ float  exA[2 * NTH];   // neighbor-exchange ping
    __shared__ float  exB[2 * NTH];   // neighbor-exchange pong
    __shared__ float  sm4[NTH];       // tail signal (levels 4-10)

    const int t = threadIdx.x;
    const float* src = in  + (size_t)blockIdx.x * DWT_N;
    float*       dst = out + (size_t)blockIdx.x * DWT_N;

    // ---- stage row: fully coalesced gmem read -> padded smem ----
    {
        const float4* src4 = reinterpret_cast<const float4*>(src);
        #pragma unroll
        for (int i = 0; i < 4; ++i) {
            int w = t + NTH * i;              // float4 index in row
            st[w + (w >> 2)] = src4[w];       // padded: conflict-managed
        }
    }
    __syncthreads();

    // ---- read my 16 contiguous floats: conflict-free LDS.128 ----
    float v[16];
    #pragma unroll
    for (int j = 0; j < 4; ++j) {
        float4 f = st[5 * t + j];             // (4t+j) + ((4t+j)>>2) = 5t+j
        v[4*j+0] = f.x; v[4*j+1] = f.y; v[4*j+2] = f.z; v[4*j+3] = f.w;
    }

    // ================= level 0 (L=4096): periodic wrap =================
    *reinterpret_cast<float2*>(&exA[2 * t]) = make_float2(v[0], v[1]);
    __syncthreads();
    float2 nb = *reinterpret_cast<const float2*>(&exA[2 * ((t + 1) & (NTH - 1))]);

    float a0[8], d0[8];
    #pragma unroll
    for (int k = 0; k < 8; ++k) {
        float x2 = (2*k + 2 < 16) ? v[2*k + 2] : nb.x;
        float x3 = (2*k + 3 < 16) ? v[2*k + 3] : nb.y;
        dwt_pair(v[2*k], v[2*k + 1], x2, x3, a0[k], d0[k]);
    }
    {   // d0 -> out[2048 + 8t ..), final
        float4* o4 = reinterpret_cast<float4*>(dst + 2048 + 8 * t);
        o4[0] = make_float4(d0[0], d0[1], d0[2], d0[3]);
        o4[1] = make_float4(d0[4], d0[5], d0[6], d0[7]);
    }

    // ================= level 1 (L=2048): truncated =================
    *reinterpret_cast<float2*>(&exB[2 * t]) = make_float2(a0[0], a0[1]);
    __syncthreads();
    nb = (t == NTH - 1) ? make_float2(0.f, 0.f)
                        : *reinterpret_cast<const float2*>(&exB[2 * (t + 1)]);

    float a1[4], d1[4];
    #pragma unroll
    for (int k = 0; k < 4; ++k) {
        float x2 = (2*k + 2 < 8) ? a0[2*k + 2] : nb.x;
        float x3 = (2*k + 3 < 8) ? a0[2*k + 3] : nb.y;
        dwt_pair(a0[2*k], a0[2*k + 1], x2, x3, a1[k], d1[k]);
    }
    *reinterpret_cast<float4*>(dst + 1024 + 4 * t) =
        make_float4(d1[0], d1[1], d1[2], d1[3]);

    // ================= level 2 (L=1024): truncated =================
    *reinterpret_cast<float2*>(&exA[2 * t]) = make_float2(a1[0], a1[1]);
    __syncthreads();
    nb = (t == NTH - 1) ? make_float2(0.f, 0.f)
                        : *reinterpret_cast<const float2*>(&exA[2 * (t + 1)]);

    float a2[2], d2[2];
    #pragma unroll
    for (int k = 0; k < 2; ++k) {
        float x2 = (2*k + 2 < 4) ? a1[2*k + 2] : nb.x;
        float x3 = (2*k + 3 < 4) ? a1[2*k + 3] : nb.y;
        dwt_pair(a1[2*k], a1[2*k + 1], x2, x3, a2[k], d2[k]);
    }
    *reinterpret_cast<float2*>(dst + 512 + 2 * t) = make_float2(d2[0], d2[1]);

    // ================= level 3 (L=512): truncated =================
    *reinterpret_cast<float2*>(&exB[2 * t]) = make_float2(a2[0], a2[1]);
    __syncthreads();
    nb = (t == NTH - 1) ? make_float2(0.f, 0.f)
                        : *reinterpret_cast<const float2*>(&exB[2 * (t + 1)]);

    float a3, d3;
    dwt_pair(a2[0], a2[1], nb.x, nb.y, a3, d3);
    dst[256 + t] = d3;

    // ---- hand the 256 remaining a-values to warp 0 ----
    sm4[t] = a3;
    __syncthreads();

    if (t < 32) {
        // levels 4-10 on sm4[0:256), in place, warp-synchronous
        #pragma unroll
        for (int l = 0; l < 7; ++l) {
            const int L = 256 >> l;
            const int H = L >> 1;
            float ra[4], rd[4];
            int cnt = 0;
            #pragma unroll
            for (int k = t; k < H; k += 32) {
                float x0 = sm4[2*k],     x1 = sm4[2*k + 1];
                float x2 = (2*k + 2 < L) ? sm4[2*k + 2] : 0.f;
                float x3 = (2*k + 3 < L) ? sm4[2*k + 3] : 0.f;
                dwt_pair(x0, x1, x2, x3, ra[cnt], rd[cnt]);
                ++cnt;
            }
            __syncwarp();
            cnt = 0;
            #pragma unroll
            for (int k = t; k < H; k += 32) {
                sm4[k]     = ra[cnt];
                sm4[H + k] = rd[cnt];
                ++cnt;
            }
            __syncwarp();
        }
        // out[0:256) final
        #pragma unroll
        for (int i = t; i < 64; i += 32)
            reinterpret_cast<float4*>(dst)[i] =
                reinterpret_cast<const float4*>(sm4)[i];
    }
}

extern "C" void kernel_launch(void* const* d_in, const int* in_sizes, int n_in,
                              void* d_out, int out_size)
{
    const float* x = (const float*)d_in[0];   // [B, N] float32
    // d_in[1] = W : structure known analytically; unused.
    float* out = (float*)d_out;

    const int B = in_sizes[0] / DWT_N;        // 4096 rows
    dwt_db4_staged_kernel<<<B, NTH>>>(x, out);
}

// round 8
// speedup vs baseline: 1.3246x; 1.1120x over previous
#include <cuda_runtime.h>
#include <cuda_bf16.h>

// Multilevel DB4 DWT (11 levels), register-resident cascade.
// 512 threads/CTA, thread t owns x[8t..8t+8) (2x LDG.128, 32B lane stride).
// Levels 0-2 in registers (2-float neighbor exchange via smem per level),
// d-outputs stored straight to global fully coalesced. Level 3 via smem with
// 256 threads; levels 4-10 (256 values) by warp 0.
//
// Boundary (matches reference W[:L,:L] slicing):
//   level 0 : periodic wrap; level >=1: taps beyond L are zero.

#define DWT_N 4096
#define NTH   512

__device__ __forceinline__ void dwt_pair(float x0, float x1, float x2, float x3,
                                         float& a, float& d)
{
    const float c0 =  0.4829629131445341f;
    const float c1 =  0.8365163037378079f;
    const float c2 =  0.2241438680420134f;
    const float c3 = -0.1294095225512604f;
    a = c0 * x0 + c1 * x1 + c2 * x2 + c3 * x3;
    d = c3 * x0 - c2 * x1 + c1 * x2 - c0 * x3;
}

__global__ __launch_bounds__(NTH)
void dwt_db4_reg512_kernel(const float* __restrict__ in,
                           float* __restrict__ out)
{
    __shared__ float exA[2 * NTH];   // exchange ping (4KB)
    __shared__ float exB[2 * NTH];   // exchange pong (4KB)
    __shared__ float sm3[NTH];       // level-3 input (512 floats)
    __shared__ float sm4[NTH / 2];   // levels 4-10 signal (256 floats)

    const int t = threadIdx.x;
    const float* src = in  + (size_t)blockIdx.x * DWT_N;
    float*       dst = out + (size_t)blockIdx.x * DWT_N;

    // ---- load chunk x[8t .. 8t+8) : 2x LDG.128 ----
    float v[8];
    {
        const float4* s4 = reinterpret_cast<const float4*>(src) + 2 * t;
        float4 f0 = s4[0];
        float4 f1 = s4[1];
        v[0] = f0.x; v[1] = f0.y; v[2] = f0.z; v[3] = f0.w;
        v[4] = f1.x; v[5] = f1.y; v[6] = f1.z; v[7] = f1.w;
    }

    // ================= level 0 (L=4096): periodic wrap =================
    *reinterpret_cast<float2*>(&exA[2 * t]) = make_float2(v[0], v[1]);
    __syncthreads();
    float2 nb = *reinterpret_cast<const float2*>(&exA[2 * ((t + 1) & (NTH - 1))]);

    float a0[4], d0[4];
    #pragma unroll
    for (int k = 0; k < 4; ++k) {
        float x2 = (2*k + 2 < 8) ? v[2*k + 2] : nb.x;
        float x3 = (2*k + 3 < 8) ? v[2*k + 3] : nb.y;
        dwt_pair(v[2*k], v[2*k + 1], x2, x3, a0[k], d0[k]);
    }
    // d0 -> out[2048 + 4t), float4, 16B lane stride: perfectly coalesced
    *reinterpret_cast<float4*>(dst + 2048 + 4 * t) =
        make_float4(d0[0], d0[1], d0[2], d0[3]);

    // ================= level 1 (L=2048): truncated =================
    *reinterpret_cast<float2*>(&exB[2 * t]) = make_float2(a0[0], a0[1]);
    __syncthreads();
    nb = (t == NTH - 1) ? make_float2(0.f, 0.f)
                        : *reinterpret_cast<const float2*>(&exB[2 * (t + 1)]);

    float a1[2], d1[2];
    #pragma unroll
    for (int k = 0; k < 2; ++k) {
        float x2 = (2*k + 2 < 4) ? a0[2*k + 2] : nb.x;
        float x3 = (2*k + 3 < 4) ? a0[2*k + 3] : nb.y;
        dwt_pair(a0[2*k], a0[2*k + 1], x2, x3, a1[k], d1[k]);
    }
    *reinterpret_cast<float2*>(dst + 1024 + 2 * t) = make_float2(d1[0], d1[1]);

    // ================= level 2 (L=1024): truncated =================
    *reinterpret_cast<float2*>(&exA[2 * t]) = make_float2(a1[0], a1[1]);
    __syncthreads();
    nb = (t == NTH - 1) ? make_float2(0.f, 0.f)
                        : *reinterpret_cast<const float2*>(&exA[2 * (t + 1)]);

    float a2, d2;
    dwt_pair(a1[0], a1[1], nb.x, nb.y, a2, d2);
    dst[512 + t] = d2;

    // ---- a2 (512 values) -> smem for level 3 ----
    sm3[t] = a2;
    __syncthreads();

    // ================= level 3 (L=512): truncated, 256 threads ==========
    if (t < 256) {
        float x0 = sm3[2*t], x1 = sm3[2*t + 1];
        float x2 = (2*t + 2 < 512) ? sm3[2*t + 2] : 0.f;
        float x3 = (2*t + 3 < 512) ? sm3[2*t + 3] : 0.f;
        float a3, d3;
        dwt_pair(x0, x1, x2, x3, a3, d3);
        dst[256 + t] = d3;
        sm4[t] = a3;
    }
    __syncthreads();

    // ================= levels 4-10 on sm4[0:256): warp 0 ================
    if (t < 32) {
        #pragma unroll
        for (int l = 0; l < 7; ++l) {
            const int L = 256 >> l;
            const int H = L >> 1;
            float ra[4], rd[4];
            int cnt = 0;
            #pragma unroll
            for (int k = t; k < H; k += 32) {
                float x0 = sm4[2*k],     x1 = sm4[2*k + 1];
                float x2 = (2*k + 2 < L) ? sm4[2*k + 2] : 0.f;
                float x3 = (2*k + 3 < L) ? sm4[2*k + 3] : 0.f;
                dwt_pair(x0, x1, x2, x3, ra[cnt], rd[cnt]);
                ++cnt;
            }
            __syncwarp();
            cnt = 0;
            #pragma unroll
            for (int k = t; k < H; k += 32) {
                sm4[k]     = ra[cnt];
                sm4[H + k] = rd[cnt];
                ++cnt;
            }
            __syncwarp();
        }
        // out[0:256) final
        #pragma unroll
        for (int i = t; i < 64; i += 32)
            reinterpret_cast<float4*>(dst)[i] =
                reinterpret_cast<const float4*>(sm4)[i];
    }
}

extern "C" void kernel_launch(void* const* d_in, const int* in_sizes, int n_in,
                              void* d_out, int out_size)
{
    const float* x = (const float*)d_in[0];   // [B, N] float32
    // d_in[1] = W : structure known analytically; unused.
    float* out = (float*)d_out;

    const int B = in_sizes[0] / DWT_N;        // 4096 rows
    dwt_db4_reg512_kernel<<<B, NTH>>>(x, out);
}

// round 11
// speedup vs baseline: 1.3964x; 1.0542x over previous
#include <cuda_runtime.h>
#include <cuda_bf16.h>

// Multilevel DB4 DWT (11 levels), register cascade, TWO rows per CTA.
// 512 threads/CTA; thread t owns x[8t..8t+8) of rows 2b and 2b+1.
// All 4 row-loads issued before the first barrier (deep MLP); the 5
// __syncthreads cover both rows; tail levels run on separate warps per row.
// Streaming cache hints: __ldcs on input (read once), __stcs on output
// (written once, never re-read) -> no L2 write-allocate pollution.
//
// Boundary (matches reference W[:L,:L] slicing):
//   level 0 : periodic wrap; level >=1: taps beyond L are zero.

#define DWT_N 4096
#define NTH   512

__device__ __forceinline__ void dwt_pair(float x0, float x1, float x2, float x3,
                                         float& a, float& d)
{
    const float c0 =  0.4829629131445341f;
    const float c1 =  0.8365163037378079f;
    const float c2 =  0.2241438680420134f;
    const float c3 = -0.1294095225512604f;
    a = c0 * x0 + c1 * x1 + c2 * x2 + c3 * x3;
    d = c3 * x0 - c2 * x1 + c1 * x2 - c0 * x3;
}

__global__ __launch_bounds__(NTH, 2)
void dwt_db4_2row_kernel(const float* __restrict__ in,
                         float* __restrict__ out)
{
    __shared__ float exA[2 * NTH * 2];   // exchange ping, both rows (8KB)
    __shared__ float exB[2 * NTH * 2];   // exchange pong, both rows (8KB)
    __shared__ float sm3[2][NTH];        // level-3 inputs (4KB)
    __shared__ float sm4[2][NTH / 2];    // levels 4-10 signals (2KB)

    const int t = threadIdx.x;
    const size_t rowA = 2 * (size_t)blockIdx.x;
    const float* srcA = in  + rowA * DWT_N;
    const float* srcB = srcA + DWT_N;
    float*       dstA = out + rowA * DWT_N;
    float*       dstB = dstA + DWT_N;

    // ---- 4 back-to-back LDG.128 (streaming): both rows in flight ----
    float vA[8], vB[8];
    {
        const float4* a4 = reinterpret_cast<const float4*>(srcA) + 2 * t;
        const float4* b4 = reinterpret_cast<const float4*>(srcB) + 2 * t;
        float4 fa0 = __ldcs(a4 + 0);
        float4 fa1 = __ldcs(a4 + 1);
        float4 fb0 = __ldcs(b4 + 0);
        float4 fb1 = __ldcs(b4 + 1);
        vA[0]=fa0.x; vA[1]=fa0.y; vA[2]=fa0.z; vA[3]=fa0.w;
        vA[4]=fa1.x; vA[5]=fa1.y; vA[6]=fa1.z; vA[7]=fa1.w;
        vB[0]=fb0.x; vB[1]=fb0.y; vB[2]=fb0.z; vB[3]=fb0.w;
        vB[4]=fb1.x; vB[5]=fb1.y; vB[6]=fb1.z; vB[7]=fb1.w;
    }

    // ================= level 0 (L=4096): periodic wrap =================
    *reinterpret_cast<float2*>(&exA[2 * t])           = make_float2(vA[0], vA[1]);
    *reinterpret_cast<float2*>(&exA[2*NTH + 2 * t])   = make_float2(vB[0], vB[1]);
    __syncthreads();
    const int tn = 2 * ((t + 1) & (NTH - 1));
    float2 nbA = *reinterpret_cast<const float2*>(&exA[tn]);
    float2 nbB = *reinterpret_cast<const float2*>(&exA[2*NTH + tn]);

    float a0A[4], d0A[4], a0B[4], d0B[4];
    #pragma unroll
    for (int k = 0; k < 4; ++k) {
        float x2 = (2*k + 2 < 8) ? vA[2*k + 2] : nbA.x;
        float x3 = (2*k + 3 < 8) ? vA[2*k + 3] : nbA.y;
        dwt_pair(vA[2*k], vA[2*k + 1], x2, x3, a0A[k], d0A[k]);
        float y2 = (2*k + 2 < 8) ? vB[2*k + 2] : nbB.x;
        float y3 = (2*k + 3 < 8) ? vB[2*k + 3] : nbB.y;
        dwt_pair(vB[2*k], vB[2*k + 1], y2, y3, a0B[k], d0B[k]);
    }
    __stcs(reinterpret_cast<float4*>(dstA + 2048 + 4 * t),
           make_float4(d0A[0], d0A[1], d0A[2], d0A[3]));
    __stcs(reinterpret_cast<float4*>(dstB + 2048 + 4 * t),
           make_float4(d0B[0], d0B[1], d0B[2], d0B[3]));

    // ================= level 1 (L=2048): truncated =================
    *reinterpret_cast<float2*>(&exB[2 * t])         = make_float2(a0A[0], a0A[1]);
    *reinterpret_cast<float2*>(&exB[2*NTH + 2 * t]) = make_float2(a0B[0], a0B[1]);
    __syncthreads();
    if (t == NTH - 1) { nbA = make_float2(0.f, 0.f); nbB = nbA; }
    else {
        nbA = *reinterpret_cast<const float2*>(&exB[2 * (t + 1)]);
        nbB = *reinterpret_cast<const float2*>(&exB[2*NTH + 2 * (t + 1)]);
    }

    float a1A[2], d1A[2], a1B[2], d1B[2];
    #pragma unroll
    for (int k = 0; k < 2; ++k) {
        float x2 = (2*k + 2 < 4) ? a0A[2*k + 2] : nbA.x;
        float x3 = (2*k + 3 < 4) ? a0A[2*k + 3] : nbA.y;
        dwt_pair(a0A[2*k], a0A[2*k + 1], x2, x3, a1A[k], d1A[k]);
        float y2 = (2*k + 2 < 4) ? a0B[2*k + 2] : nbB.x;
        float y3 = (2*k + 3 < 4) ? a0B[2*k + 3] : nbB.y;
        dwt_pair(a0B[2*k], a0B[2*k + 1], y2, y3, a1B[k], d1B[k]);
    }
    __stcs(reinterpret_cast<float2*>(dstA + 1024 + 2 * t),
           make_float2(d1A[0], d1A[1]));
    __stcs(reinterpret_cast<float2*>(dstB + 1024 + 2 * t),
           make_float2(d1B[0], d1B[1]));

    // ================= level 2 (L=1024): truncated =================
    *reinterpret_cast<float2*>(&exA[2 * t])         = make_float2(a1A[0], a1A[1]);
    *reinterpret_cast<float2*>(&exA[2*NTH + 2 * t]) = make_float2(a1B[0], a1B[1]);
    __syncthreads();
    if (t == NTH - 1) { nbA = make_float2(0.f, 0.f); nbB = nbA; }
    else {
        nbA = *reinterpret_cast<const float2*>(&exA[2 * (t + 1)]);
        nbB = *reinterpret_cast<const float2*>(&exA[2*NTH + 2 * (t + 1)]);
    }

    float a2A, d2A, a2B, d2B;
    dwt_pair(a1A[0], a1A[1], nbA.x, nbA.y, a2A, d2A);
    dwt_pair(a1B[0], a1B[1], nbB.x, nbB.y, a2B, d2B);
    __stcs(dstA + 512 + t, d2A);
    __stcs(dstB + 512 + t, d2B);

    // ---- a2 (512 values/row) -> smem for level 3 ----
    sm3[0][t] = a2A;
    sm3[1][t] = a2B;
    __syncthreads();

    // ========== level 3 (L=512): 256 threads per row, in parallel =======
    {
        const int r = (t < 256) ? 0 : 1;
        const int k = t & 255;
        float* drow = r ? dstB : dstA;
        float x0 = sm3[r][2*k], x1 = sm3[r][2*k + 1];
        float x2 = (2*k + 2 < 512) ? sm3[r][2*k + 2] : 0.f;
        float x3 = (2*k + 3 < 512) ? sm3[r][2*k + 3] : 0.f;
        float a3, d3;
        dwt_pair(x0, x1, x2, x3, a3, d3);
        __stcs(drow + 256 + k, d3);
        sm4[r][k] = a3;
    }
    __syncthreads();

    // ===== levels 4-10: warp 0 -> row A, warp 1 -> row B, concurrent =====
    if (t < 64) {
        const int r    = t >> 5;          // warp id: 0 -> row A, 1 -> row B
        const int lane = t & 31;
        float* srow = sm4[r];
        float* drow = r ? dstB : dstA;

        #pragma unroll
        for (int l = 0; l < 7; ++l) {
            const int L = 256 >> l;
            const int H = L >> 1;
            float ra[4], rd[4];
            int cnt = 0;
            #pragma unroll
            for (int k = lane; k < H; k += 32) {
                float x0 = srow[2*k],     x1 = srow[2*k + 1];
                float x2 = (2*k + 2 < L) ? srow[2*k + 2] : 0.f;
                float x3 = (2*k + 3 < L) ? srow[2*k + 3] : 0.f;
                dwt_pair(x0, x1, x2, x3, ra[cnt], rd[cnt]);
                ++cnt;
            }
            __syncwarp();
            cnt = 0;
            #pragma unroll
            for (int k = lane; k < H; k += 32) {
                srow[k]     = ra[cnt];
                srow[H + k] = rd[cnt];
                ++cnt;
            }
            __syncwarp();
        }
        // out[0:256) final
        #pragma unroll
        for (int i = lane; i < 64; i += 32)
            __stcs(reinterpret_cast<float4*>(drow) + i,
                   reinterpret_cast<const float4*>(srow)[i]);
    }
}

extern "C" void kernel_launch(void* const* d_in, const int* in_sizes, int n_in,
                              void* d_out, int out_size)
{
    const float* x = (const float*)d_in[0];   // [B, N] float32
    // d_in[1] = W : structure known analytically; unused.
    float* out = (float*)d_out;

    const int B = in_sizes[0] / DWT_N;        // 4096 rows
    dwt_db4_2row_kernel<<<B / 2, NTH>>>(x, out);
}